// round 12
// baseline (speedup 1.0000x reference)
#include <cuda_runtime.h>
#include <cstdint>

// FirstFFTLinearLayer: 64-point forward complex DFT along dim 1 of
// [B=16, N=64, H=256, W=256] f32 (separate real/imag inputs).
// Output: REAL PART only, f32, [B, N, H, W]. (Established R1-R9.)
//
// R9 (121.3us, DRAM 81.7%) is the best structure: batched loads, full
// in-register FFT. R10/R11 restructures both regressed. Binding limit is
// registers (151 -> 12 warps/SM). This round: identical R9 dataflow +
// __launch_bounds__(128, 4) to cap regs at 128 -> 16 warps/SM; the ~20-reg
// spill working set (~47 KB/SM) stays L1-resident (L1 is 33% busy, and the
// streaming data it evicts has zero reuse).

#define HW 65536          // H*W
#define NFFT 64
#define BATCH 16
#define NPIX (BATCH * HW) // 1,048,576

__global__ __launch_bounds__(128, 4)
void fft64_kernel(const float* __restrict__ re,
                  const float* __restrict__ im,
                  float* __restrict__ out) {
    __shared__ float2 tw[NFFT];
    {
        int t = threadIdx.x;
        if (t < NFFT) {
            float s, c;
            // exp(-2*pi*i*t/64) = cos(pi t/32) - i sin(pi t/32)
            sincospif(-(float)t * (1.0f / 32.0f), &s, &c);
            tw[t] = make_float2(c, s);
        }
    }
    __syncthreads();

    int idx = blockIdx.x * blockDim.x + threadIdx.x;
    int s_  = idx & (HW - 1);
    int b   = idx >> 16;
    const size_t base = (size_t)b * (NFFT * (size_t)HW) + (size_t)s_;

    float xr[NFFT], xi[NFFT];
#pragma unroll
    for (int j = 0; j < NFFT; j++) {
        xr[j] = re[base + (size_t)j * HW];
        xi[j] = im[base + (size_t)j * HW];
    }

    // Radix-2 DIF (Gentleman-Sande), fully unrolled; output bit-reversed.
#define FFT_STAGE(M)                                                      \
    {                                                                     \
        constexpr int m_    = (M);                                        \
        constexpr int half_ = m_ / 2;                                     \
        constexpr int step_ = NFFT / m_;                                  \
        _Pragma("unroll")                                                 \
        for (int k = 0; k < NFFT; k += m_) {                              \
            _Pragma("unroll")                                             \
            for (int j = 0; j < half_; j++) {                             \
                float ur = xr[k + j],         ui = xi[k + j];             \
                float vr = xr[k + j + half_], vi = xi[k + j + half_];     \
                xr[k + j] = ur + vr;                                      \
                xi[k + j] = ui + vi;                                      \
                float dr = ur - vr, di = ui - vi;                         \
                float2 w = tw[(j * step_) & (NFFT - 1)];                  \
                xr[k + j + half_] = dr * w.x - di * w.y;                  \
                xi[k + j + half_] = dr * w.y + di * w.x;                  \
            }                                                             \
        }                                                                 \
    }

    FFT_STAGE(64)
    FFT_STAGE(32)
    FFT_STAGE(16)
    FFT_STAGE(8)
    FFT_STAGE(4)
    FFT_STAGE(2)
#undef FFT_STAGE

    // X[k] sits at register slot brev6(k); store REAL PART only (f32).
    float* o = out + base;
#pragma unroll
    for (int k = 0; k < NFFT; k++) {
        int p = (int)(__brev((unsigned)k) >> 26);  // 6-bit bit-reverse
        o[(size_t)k * HW] = xr[p];
    }
}

extern "C" void kernel_launch(void* const* d_in, const int* in_sizes, int n_in,
                              void* d_out, int out_size) {
    // Weight = smallest input (unused); remaining two in d_in order = (re, im).
    int wmin = 0;
    for (int i = 1; i < n_in; i++)
        if (in_sizes[i] < in_sizes[wmin]) wmin = i;

    const float* adc_real = nullptr;
    const float* adc_imag = nullptr;
    for (int i = 0; i < n_in; i++) {
        if (i == wmin) continue;
        if (!adc_real)      adc_real = (const float*)d_in[i];
        else if (!adc_imag) adc_imag = (const float*)d_in[i];
    }
    if (!adc_real || !adc_imag) return;

    float* out = (float*)d_out;
    const int threads = 128;
    const int blocks  = NPIX / threads;  // 8192
    fft64_kernel<<<blocks, threads>>>(adc_real, adc_imag, out);
}

// round 13
// speedup vs baseline: 1.3622x; 1.3622x over previous
#include <cuda_runtime.h>
#include <cstdint>

// FirstFFTLinearLayer: 64-point forward complex DFT along dim 1 of
// [B=16, N=64, H=256, W=256] f32 (separate real/imag inputs).
// Output: REAL PART only, f32, [B, N, H, W]. (Established R1-R9.)
//
// R9 = 121.3us @ DRAM 81.7%, 151 regs -> 12 warps/SM (register-bound).
// R10 (interleave), R11 (smem parking), R12 (forced spill) all regressed.
// This round: pair-split FFT. TWO adjacent lanes per pixel, 32 complex
// samples each (half the register state, no smem, no spill). One
// shfl_xor(1) per element does the stage-64 butterfly exchange; each lane
// then runs an independent in-register FFT-32. Lane-even produces even
// output bins, lane-odd produces odd bins. Every global access touches two
// contiguous 64B segments per warp -> 100% sector efficiency.

#define HW 65536          // H*W
#define NFFT 64
#define BATCH 16
#define NPIX (BATCH * HW) // 1,048,576 pixels; 2 threads per pixel
#define TPB 128

__global__ __launch_bounds__(TPB)
void fft64_kernel(const float* __restrict__ re,
                  const float* __restrict__ im,
                  float* __restrict__ out) {
    __shared__ float2 tw[NFFT];
    {
        int t = threadIdx.x;
        if (t < NFFT) {
            float s, c;
            // exp(-2*pi*i*t/64) = cos(pi t/32) - i sin(pi t/32)
            sincospif(-(float)t * (1.0f / 32.0f), &s, &c);
            tw[t] = make_float2(c, s);
        }
    }
    __syncthreads();

    const int gtid = blockIdx.x * TPB + threadIdx.x;
    const int pix  = gtid >> 1;        // pixel index (b*HW + h*W + w)
    const int half = gtid & 1;         // 0: j=0..31 (u), 1: j=32..63 (v)
    int s_ = pix & (HW - 1);
    int b  = pix >> 16;
    const size_t base = (size_t)b * (NFFT * (size_t)HW) + (size_t)s_;

    const float* pr  = re + base + (size_t)(half << 5) * HW;
    const float* pim = im + base + (size_t)(half << 5) * HW;

    // Front-batched loads: 64 independent LDGs (32 re + 32 im).
    float xr[32], xi[32];
#pragma unroll
    for (int j = 0; j < 32; j++) xr[j] = pr[(size_t)j * HW];
#pragma unroll
    for (int j = 0; j < 32; j++) xi[j] = pim[(size_t)j * HW];

    // Stage m=64 butterfly across the lane pair:
    //   lane-even holds u_j, lane-odd holds v_j (j = 0..31).
    //   even result: u+v ; odd result: (u-v) * tw[j].
#pragma unroll
    for (int j = 0; j < 32; j++) {
        float qr = __shfl_xor_sync(0xFFFFFFFFu, xr[j], 1);
        float qi = __shfl_xor_sync(0xFFFFFFFFu, xi[j], 1);
        float sr = xr[j] + qr;          // u + v   (valid on lane-even)
        float si = xi[j] + qi;
        float dr = qr - xr[j];          // u - v   (valid on lane-odd: q=u, x=v)
        float di = qi - xi[j];
        float2 w = tw[j];
        float tr = dr * w.x - di * w.y;
        float ti = dr * w.y + di * w.x;
        xr[j] = half ? tr : sr;
        xi[j] = half ? ti : si;
    }

    // Independent 32-point FFT per lane: stages m=32..2 of the 64-pt DIF
    // (twiddle step = 64/m into the shared 64-entry table).
#pragma unroll
    for (int m = 32; m >= 2; m >>= 1) {
        const int hm   = m >> 1;
        const int step = NFFT / m;
#pragma unroll
        for (int k = 0; k < 32; k += m) {
#pragma unroll
            for (int j = 0; j < hm; j++) {
                float ur = xr[k + j],      ui = xi[k + j];
                float vr = xr[k + j + hm], vi = xi[k + j + hm];
                xr[k + j] = ur + vr;
                xi[k + j] = ui + vi;
                float dr = ur - vr, di = ui - vi;
                float2 w = tw[(j * step) & (NFFT - 1)];
                xr[k + j + hm] = dr * w.x - di * w.y;
                xi[k + j + hm] = dr * w.y + di * w.x;
            }
        }
    }

    // Output bin 2r+half = slot brev5(r); store REAL part only.
    float* o = out + base + (size_t)half * HW;
#pragma unroll
    for (int r = 0; r < 32; r++) {
        int p = (int)(__brev((unsigned)r) >> 27);  // 5-bit bit-reverse
        o[(size_t)(2 * r) * HW] = xr[p];
    }
}

extern "C" void kernel_launch(void* const* d_in, const int* in_sizes, int n_in,
                              void* d_out, int out_size) {
    // Weight = smallest input (unused); remaining two in d_in order = (re, im).
    int wmin = 0;
    for (int i = 1; i < n_in; i++)
        if (in_sizes[i] < in_sizes[wmin]) wmin = i;

    const float* adc_real = nullptr;
    const float* adc_imag = nullptr;
    for (int i = 0; i < n_in; i++) {
        if (i == wmin) continue;
        if (!adc_real)      adc_real = (const float*)d_in[i];
        else if (!adc_imag) adc_imag = (const float*)d_in[i];
    }
    if (!adc_real || !adc_imag) return;

    float* out = (float*)d_out;
    const int blocks = (2 * NPIX) / TPB;  // 16384
    fft64_kernel<<<blocks, TPB>>>(adc_real, adc_imag, out);
}